// round 14
// baseline (speedup 1.0000x reference)
#include <cuda_runtime.h>
#include <cuda_bf16.h>
#include <cuda_fp16.h>
#include <cstdint>

// B=4096, D=128. out[4096][16384] fp32.
// part1 (cols 0..8191)  = softmax([a@b.T , a@a.T - diag*INF])
// part2 (cols 8192..)   = softmax([b@a.T , b@b.T - diag*INF])
// GEMM: split-bf16 (hi+lo, 3 products) on mma.sync.m16n8k16, symmetry-halved
// (2080 tiles), fp16 stage for unnormalized exp.
// Persistent kernel, NON-BLOCKING work stealing: between GEMM jobs each CTA
// opportunistically claims scale chunks whose row-block is complete (CAS,
// never spins); after the GEMM queue empties, CTAs drain remaining chunks.

#define NROWS 4096
#define DDIM  128
#define OCOLS 16384
#define NGEMM 2080
#define NSCAL 2048

__device__ float g_sums[2 * NROWS];
__device__ __align__(256) __nv_bfloat16 g_ah[NROWS * DDIM];
__device__ __align__(256) __nv_bfloat16 g_al[NROWS * DDIM];
__device__ __align__(256) __nv_bfloat16 g_bh[NROWS * DDIM];
__device__ __align__(256) __nv_bfloat16 g_bl[NROWS * DDIM];
__device__ __align__(256) __half g_stage[(size_t)NROWS * OCOLS];   // 128 MB fp16 exp stage
__device__ uint32_t g_queue[NGEMM];
__device__ unsigned int g_done[64];     // [0..31] part1 blocks, [32..63] part2
__device__ unsigned int g_qhead;
__device__ unsigned int g_shead;

// ---------------- normalize + bf16 hi/lo split + zero sums ----------------
__global__ void norm_kernel(const float* __restrict__ z1,
                            const float* __restrict__ z2) {
    int row = blockIdx.x;           // 0..8191
    int tid = threadIdx.x;          // 0..127
    const float* src; __nv_bfloat16 *dh, *dl; int r;
    if (row < NROWS) { src = z1; dh = g_ah; dl = g_al; r = row; }
    else             { src = z2; dh = g_bh; dl = g_bl; r = row - NROWS; }
    float v = src[r * DDIM + tid];
    float s = v * v;
    #pragma unroll
    for (int o = 16; o; o >>= 1) s += __shfl_xor_sync(0xffffffffu, s, o);
    __shared__ float ws[4];
    if ((tid & 31) == 0) ws[tid >> 5] = s;
    __syncthreads();
    float tot = ws[0] + ws[1] + ws[2] + ws[3];
    float vn = v * rsqrtf(fmaxf(tot, 1e-12f));
    __nv_bfloat16 h = __float2bfloat16(vn);
    float hr = __bfloat162float(h);
    __nv_bfloat16 l = __float2bfloat16(vn - hr);
    dh[r * DDIM + tid] = h;
    dl[r * DDIM + tid] = l;
    if (tid == 0) g_sums[row] = 0.0f;
}

// ---------------- queue init ----------------
// Phase1 group g (g=0..31): ab(g,0..31) then aa(g,g..31)  -> part1 block g
// completes at end of group g. Phase2 group g: bb(g,g..31) -> part2 block g.
__global__ void init_kernel() {
    int tid = threadIdx.x;
    if (tid == 0) { g_qhead = 0; g_shead = 0; }
    if (tid < 64) g_done[tid] = 0;
    for (int g = 0; g < 32; g++) {
        int b1 = 64 * g - (g * (g - 1)) / 2;
        for (int j = tid; j < 64 - g; j += 256)
            g_queue[b1 + j] = (j < 32) ? ((0u << 12) | (g << 6) | j)
                                       : ((1u << 12) | (g << 6) | (g + j - 32));
        int b2 = 1552 + 32 * g - (g * (g - 1)) / 2;
        for (int j = tid; j < 32 - g; j += 256)
            g_queue[b2 + j] = (2u << 12) | (g << 6) | (g + j);
    }
}

// ---------------- mma / cp.async helpers ----------------
__device__ __forceinline__ void ldsm4(uint32_t* r, uint32_t addr) {
    asm volatile("ldmatrix.sync.aligned.m8n8.x4.shared.b16 {%0,%1,%2,%3}, [%4];"
                 : "=r"(r[0]), "=r"(r[1]), "=r"(r[2]), "=r"(r[3]) : "r"(addr));
}
__device__ __forceinline__ void ldsm2(uint32_t* r, uint32_t addr) {
    asm volatile("ldmatrix.sync.aligned.m8n8.x2.shared.b16 {%0,%1}, [%2];"
                 : "=r"(r[0]), "=r"(r[1]) : "r"(addr));
}
__device__ __forceinline__ void mma16816(float* d, const uint32_t* a, const uint32_t* b) {
    asm volatile(
        "mma.sync.aligned.m16n8k16.row.col.f32.bf16.bf16.f32 "
        "{%0,%1,%2,%3}, {%4,%5,%6,%7}, {%8,%9}, {%0,%1,%2,%3};"
        : "+f"(d[0]), "+f"(d[1]), "+f"(d[2]), "+f"(d[3])
        : "r"(a[0]), "r"(a[1]), "r"(a[2]), "r"(a[3]), "r"(b[0]), "r"(b[1]));
}
__device__ __forceinline__ void cpa16(uint32_t dst, const void* src) {
    asm volatile("cp.async.cg.shared.global [%0], [%1], 16;" :: "r"(dst), "l"(src));
}
#define CP_COMMIT() asm volatile("cp.async.commit_group;")
#define CP_WAIT(n)  asm volatile("cp.async.wait_group %0;" :: "n"(n))

__device__ __forceinline__ uint32_t swz(int row, int chunk) {
    return (uint32_t)(row * 256 + ((chunk ^ (row & 7)) << 4));
}

// SMEM: P=Ah (resident), Q=Bh, R=Al then Bl. 32 KB each.
#define SM_P 0
#define SM_Q 32768
#define SM_R 65536
#define SM_RS 98304
#define SM_CS 98816
#define SM_TOTAL 99328
#define TSTRIDE 136   // words; conflict-free half2 transpose scatter

// ---------------- scale chunk: 4 rows x 8192 cols of one part ----------------
__device__ __forceinline__ void do_scale_chunk(uint32_t s, float* __restrict__ out,
                                               int tid) {
    __threadfence();                        // acquire vs producer release
    int p   = s >> 10;
    int blk = (s >> 5) & 31;
    int sub = s & 31;
    int r0 = blk * 128 + sub * 4;
    #pragma unroll
    for (int rr = 0; rr < 4; rr++) {
        int grow = r0 + rr;
        float inv = __frcp_rn(g_sums[p * NROWS + grow]);
        const uint2* src = (const uint2*)(g_stage + (size_t)grow * OCOLS + p * 8192);
        float4* dst = (float4*)out + (size_t)grow * 4096 + p * 2048;
        #pragma unroll
        for (int it = 0; it < 8; it++) {
            int j = tid + it * 256;
            uint2 st = src[j];
            __half2 p0 = *reinterpret_cast<__half2*>(&st.x);
            __half2 p1 = *reinterpret_cast<__half2*>(&st.y);
            float2 f0 = __half22float2(p0);
            float2 f1 = __half22float2(p1);
            dst[j] = make_float4(f0.x * inv, f0.y * inv, f1.x * inv, f1.y * inv);
        }
    }
}

// ---------------- persistent mega kernel ----------------
__global__ void __launch_bounds__(256, 2)
mega_kernel(float* __restrict__ out) {
    extern __shared__ char smem[];
    __shared__ uint32_t s_job, s_scale;
    uint32_t sb = (uint32_t)__cvta_generic_to_shared(smem);
    float* rs_s = (float*)(smem + SM_RS);
    float* cs_s = (float*)(smem + SM_CS);
    int tid = threadIdx.x, wid = tid >> 5, lane = tid & 31;
    int wm = wid & 1, wn = wid >> 1;
    int g8 = lane & 7, sel = lane >> 3;
    int qr = lane >> 2, qc = (lane & 3) * 2;

    while (true) {
        // ---- opportunistic, NON-blocking scale claim ----
        if (tid == 0) {
            uint32_t c = 0xFFFFFFFFu;
            unsigned s = atomicAdd(&g_shead, 0u);
            if (s < NSCAL && atomicAdd(&g_done[s >> 5], 0u) >= 64u)
                if (atomicCAS(&g_shead, s, s + 1u) == s) c = s;
            s_scale = c;
        }
        __syncthreads();
        uint32_t sc = s_scale;
        __syncthreads();
        if (sc != 0xFFFFFFFFu) {
            do_scale_chunk(sc, out, tid);
            continue;
        }

        // ---- gemm job ----
        if (tid == 0) {
            unsigned q = atomicAdd(&g_qhead, 1u);
            s_job = (q < NGEMM) ? g_queue[q] : 0xFFFFFFFFu;
        }
        __syncthreads();
        uint32_t jd = s_job;
        __syncthreads();
        if (jd == 0xFFFFFFFFu) break;     // gemm done -> drain phase

        {
            int job = (jd >> 12) & 3;            // 0=ab 1=aa 2=bb
            int ti  = (jd >> 6) & 63;
            int tj  = jd & 63;
            const __nv_bfloat16* Lh = (job == 2) ? g_bh : g_ah;
            const __nv_bfloat16* Ll = (job == 2) ? g_bl : g_al;
            const __nv_bfloat16* Rh = (job == 1) ? g_ah : g_bh;
            const __nv_bfloat16* Rl = (job == 1) ? g_al : g_bl;
            bool diag = (job != 0) && (ti == tj);
            bool doT  = (job == 0) || (ti != tj);
            int quadP = (job == 0) ? 0 : (job == 1 ? 4096 : 12288);
            int quadT = (job == 0) ? 8192 : quadP;
            int colP = quadP + tj * 128;
            int colT = quadT + ti * 128;
            int sumP = (job == 2) ? NROWS : 0;
            int sumT = (job == 1) ? 0 : NROWS;

            const __nv_bfloat16* Ah = Lh + ti * 128 * DDIM;
            const __nv_bfloat16* Al = Ll + ti * 128 * DDIM;
            const __nv_bfloat16* Bh = Rh + tj * 128 * DDIM;
            const __nv_bfloat16* Bl = Rl + tj * 128 * DDIM;

            if (tid < 128) { rs_s[tid] = 0.0f; cs_s[tid] = 0.0f; }

            #pragma unroll
            for (int it = 0; it < 8; it++) {
                int i = tid + it * 256;
                int r = i >> 4, c = i & 15;
                uint32_t so = swz(r, c);
                cpa16(sb + SM_P + so, Ah + r * DDIM + c * 8);
                cpa16(sb + SM_Q + so, Bh + r * DDIM + c * 8);
            }
            CP_COMMIT();
            #pragma unroll
            for (int it = 0; it < 8; it++) {
                int i = tid + it * 256;
                int r = i >> 4, c = i & 15;
                cpa16(sb + SM_R + swz(r, c), Al + r * DDIM + c * 8);
            }
            CP_COMMIT();

            float acc[16][4];
            #pragma unroll
            for (int i = 0; i < 16; i++)
                #pragma unroll
                for (int j = 0; j < 4; j++) acc[i][j] = 0.0f;

            auto mma_pass = [&](uint32_t abase, uint32_t bbase) {
                #pragma unroll
                for (int ks = 0; ks < 8; ks++) {
                    int kc = ks * 2;
                    uint32_t af[4][4], bf[4][2];
                    #pragma unroll
                    for (int mt = 0; mt < 4; mt++) {
                        int row = wm * 64 + mt * 16 + g8 + ((sel & 1) << 3);
                        ldsm4(af[mt], abase + swz(row, kc + (sel >> 1)));
                    }
                    #pragma unroll
                    for (int nt = 0; nt < 4; nt++) {
                        int row = wn * 32 + nt * 8 + g8;
                        ldsm2(bf[nt], bbase + swz(row, kc + (sel & 1)));
                    }
                    #pragma unroll
                    for (int mt = 0; mt < 4; mt++)
                        #pragma unroll
                        for (int nt = 0; nt < 4; nt++)
                            mma16816(acc[mt * 4 + nt], af[mt], bf[nt]);
                }
            };

            CP_WAIT(1);
            __syncthreads();
            mma_pass(sb + SM_P, sb + SM_Q);          // hh
            CP_WAIT(0);
            __syncthreads();
            mma_pass(sb + SM_R, sb + SM_Q);          // lh
            __syncthreads();
            #pragma unroll
            for (int it = 0; it < 8; it++) {
                int i = tid + it * 256;
                int r = i >> 4, c = i & 15;
                cpa16(sb + SM_R + swz(r, c), Bl + r * DDIM + c * 8);
            }
            CP_COMMIT();
            CP_WAIT(0);
            __syncthreads();
            mma_pass(sb + SM_P, sb + SM_R);          // hl
            __syncthreads();

            // exp + diag mask
            #pragma unroll
            for (int mt = 0; mt < 4; mt++)
                #pragma unroll
                for (int nt = 0; nt < 4; nt++) {
                    float* a = acc[mt * 4 + nt];
                    #pragma unroll
                    for (int j = 0; j < 4; j++) a[j] = __expf(a[j] * 10.0f);
                    if (diag) {
                        int cl = wn * 32 + nt * 8 + qc;
                        #pragma unroll
                        for (int h = 0; h < 2; h++) {
                            int rl = wm * 64 + mt * 16 + h * 8 + qr;
                            if (cl == rl)     a[h * 2 + 0] = 0.0f;
                            if (cl + 1 == rl) a[h * 2 + 1] = 0.0f;
                        }
                    }
                }

            // primary fp16 stores + row sums
            #pragma unroll
            for (int mt = 0; mt < 4; mt++) {
                #pragma unroll
                for (int h = 0; h < 2; h++) {
                    int rloc = wm * 64 + mt * 16 + h * 8 + qr;
                    int grow = ti * 128 + rloc;
                    __half* rowp = g_stage + (size_t)grow * OCOLS + colP;
                    float rsum = 0.0f;
                    #pragma unroll
                    for (int nt = 0; nt < 4; nt++) {
                        int cloc = wn * 32 + nt * 8 + qc;
                        const float* a = acc[mt * 4 + nt];
                        float v0 = a[h * 2 + 0], v1 = a[h * 2 + 1];
                        rsum += v0 + v1;
                        *(__half2*)(rowp + cloc) = __floats2half2_rn(v0, v1);
                    }
                    rsum += __shfl_xor_sync(0xffffffffu, rsum, 1);
                    rsum += __shfl_xor_sync(0xffffffffu, rsum, 2);
                    if ((lane & 3) == 0) atomicAdd(&rs_s[rloc], rsum);
                }
            }

            // column sums
            #pragma unroll
            for (int nt = 0; nt < 4; nt++) {
                float c0s = 0.0f, c1s = 0.0f;
                #pragma unroll
                for (int mt = 0; mt < 4; mt++) {
                    const float* a = acc[mt * 4 + nt];
                    c0s += a[0] + a[2];
                    c1s += a[1] + a[3];
                }
                #pragma unroll
                for (int o = 4; o <= 16; o <<= 1) {
                    c0s += __shfl_xor_sync(0xffffffffu, c0s, o);
                    c1s += __shfl_xor_sync(0xffffffffu, c1s, o);
                }
                if (lane < 4) {
                    int cloc = wn * 32 + nt * 8 + qc;
                    atomicAdd(&cs_s[cloc], c0s);
                    atomicAdd(&cs_s[cloc + 1], c1s);
                }
            }

            // transpose stage (packed half2, conflict-free)
            if (doT) {
                uint32_t* stg = (uint32_t*)smem;
                #pragma unroll
                for (int mt = 0; mt < 4; mt++)
                    #pragma unroll
                    for (int nt = 0; nt < 4; nt++) {
                        const float* a = acc[mt * 4 + nt];
                        int cp = (wn * 32 + nt * 8 + qc) >> 1;
                        #pragma unroll
                        for (int h = 0; h < 2; h++) {
                            int rloc = wm * 64 + mt * 16 + h * 8 + qr;
                            __half2 hv = __floats2half2_rn(a[h * 2 + 0], a[h * 2 + 1]);
                            stg[cp * TSTRIDE + rloc] = *reinterpret_cast<uint32_t*>(&hv);
                        }
                    }
            }
            __syncthreads();

            if (doT) {
                const uint32_t* stg = (const uint32_t*)smem;
                #pragma unroll
                for (int rr = 0; rr < 8; rr++) {
                    int cp = wid * 8 + rr;
                    uint4 q = *(const uint4*)(stg + cp * TSTRIDE + lane * 4);
                    uint32_t l0 = __byte_perm(q.x, q.y, 0x5410);
                    uint32_t l1 = __byte_perm(q.z, q.w, 0x5410);
                    uint32_t h0 = __byte_perm(q.x, q.y, 0x7632);
                    uint32_t h1 = __byte_perm(q.z, q.w, 0x7632);
                    size_t base = (size_t)(tj * 128 + 2 * cp) * OCOLS + colT + lane * 4;
                    *(uint2*)(g_stage + base)         = make_uint2(l0, l1);
                    *(uint2*)(g_stage + base + OCOLS) = make_uint2(h0, h1);
                }
            }

            if (tid < 128) {
                atomicAdd(&g_sums[sumP + ti * 128 + tid], rs_s[tid]);
                if (doT) atomicAdd(&g_sums[sumT + tj * 128 + tid], cs_s[tid]);
            }

            // release: per-thread fence, then counter bumps
            __threadfence();
            __syncthreads();
            if (tid == 0)
                atomicAdd(&g_done[((job == 2) ? 32 : 0) + ti], 1u);
            if (tid == 1 && doT)
                atomicAdd(&g_done[((job == 1) ? 0 : 32) + tj], 1u);
        }
    }

    // ---- drain phase: all gemm jobs popped; blocking waits are bounded ----
    while (true) {
        if (tid == 0) s_scale = atomicAdd(&g_shead, 1u);
        __syncthreads();
        uint32_t s = s_scale;
        __syncthreads();
        if (s >= NSCAL) return;
        if (tid == 0)
            while (atomicAdd(&g_done[s >> 5], 0u) < 64u) __nanosleep(100);
        __syncthreads();
        do_scale_chunk(s, out, tid);
    }
}

extern "C" void kernel_launch(void* const* d_in, const int* in_sizes, int n_in,
                              void* d_out, int out_size) {
    const float* z1 = (const float*)d_in[0];
    const float* z2 = (const float*)d_in[1];
    float* out = (float*)d_out;

    cudaFuncSetAttribute(mega_kernel,
                         cudaFuncAttributeMaxDynamicSharedMemorySize, SM_TOTAL);

    norm_kernel<<<2 * NROWS, 128>>>(z1, z2);
    init_kernel<<<1, 256>>>();
    mega_kernel<<<304, 256, SM_TOTAL>>>(out);
}

// round 15
// speedup vs baseline: 1.8490x; 1.8490x over previous
#include <cuda_runtime.h>
#include <cuda_bf16.h>
#include <cstdint>

// B=4096, D=128. out[4096][16384] fp32.
// part1 (cols 0..8191)  = softmax([a@b.T , a@a.T - diag*INF])
// part2 (cols 8192..)   = softmax([b@a.T , b@b.T - diag*INF])
// Two-pass recompute scheme (no staging buffer):
//   pass 1: single-product bf16 HMMA -> exp -> row/col sums only (sums
//           tolerate ~2e-3 per-element error; averaging -> ~1.3e-4 on sums)
//   pass 2: 3-product split-bf16 HMMA (hi+lo) -> exp -> scale by 1/sum ->
//           fp32 writes straight to d_out (primary + transposed).
// Symmetry: ba = ab^T, aa/bb symmetric -> 2080 tiles per pass.

#define NROWS 4096
#define DDIM  128
#define OCOLS 16384

__device__ float g_sums[2 * NROWS];
__device__ __align__(256) __nv_bfloat16 g_ah[NROWS * DDIM];
__device__ __align__(256) __nv_bfloat16 g_al[NROWS * DDIM];
__device__ __align__(256) __nv_bfloat16 g_bh[NROWS * DDIM];
__device__ __align__(256) __nv_bfloat16 g_bl[NROWS * DDIM];

// ---------------- normalize + bf16 hi/lo split + zero sums ----------------
__global__ void norm_kernel(const float* __restrict__ z1,
                            const float* __restrict__ z2) {
    int row = blockIdx.x;           // 0..8191
    int tid = threadIdx.x;          // 0..127
    const float* src; __nv_bfloat16 *dh, *dl; int r;
    if (row < NROWS) { src = z1; dh = g_ah; dl = g_al; r = row; }
    else             { src = z2; dh = g_bh; dl = g_bl; r = row - NROWS; }
    float v = src[r * DDIM + tid];
    float s = v * v;
    #pragma unroll
    for (int o = 16; o; o >>= 1) s += __shfl_xor_sync(0xffffffffu, s, o);
    __shared__ float ws[4];
    if ((tid & 31) == 0) ws[tid >> 5] = s;
    __syncthreads();
    float tot = ws[0] + ws[1] + ws[2] + ws[3];
    float vn = v * rsqrtf(fmaxf(tot, 1e-12f));
    __nv_bfloat16 h = __float2bfloat16(vn);
    float hr = __bfloat162float(h);
    __nv_bfloat16 l = __float2bfloat16(vn - hr);
    dh[r * DDIM + tid] = h;
    dl[r * DDIM + tid] = l;
    if (tid == 0) g_sums[row] = 0.0f;
}

// ---------------- mma / cp.async helpers ----------------
__device__ __forceinline__ void ldsm4(uint32_t* r, uint32_t addr) {
    asm volatile("ldmatrix.sync.aligned.m8n8.x4.shared.b16 {%0,%1,%2,%3}, [%4];"
                 : "=r"(r[0]), "=r"(r[1]), "=r"(r[2]), "=r"(r[3]) : "r"(addr));
}
__device__ __forceinline__ void ldsm2(uint32_t* r, uint32_t addr) {
    asm volatile("ldmatrix.sync.aligned.m8n8.x2.shared.b16 {%0,%1}, [%2];"
                 : "=r"(r[0]), "=r"(r[1]) : "r"(addr));
}
__device__ __forceinline__ void mma16816(float* d, const uint32_t* a, const uint32_t* b) {
    asm volatile(
        "mma.sync.aligned.m16n8k16.row.col.f32.bf16.bf16.f32 "
        "{%0,%1,%2,%3}, {%4,%5,%6,%7}, {%8,%9}, {%0,%1,%2,%3};"
        : "+f"(d[0]), "+f"(d[1]), "+f"(d[2]), "+f"(d[3])
        : "r"(a[0]), "r"(a[1]), "r"(a[2]), "r"(a[3]), "r"(b[0]), "r"(b[1]));
}
__device__ __forceinline__ void cpa16(uint32_t dst, const void* src) {
    asm volatile("cp.async.cg.shared.global [%0], [%1], 16;" :: "r"(dst), "l"(src));
}
#define CP_COMMIT() asm volatile("cp.async.commit_group;")
#define CP_WAIT(n)  asm volatile("cp.async.wait_group %0;" :: "n"(n))

__device__ __forceinline__ uint32_t swz(int row, int chunk) {
    return (uint32_t)(row * 256 + ((chunk ^ (row & 7)) << 4));
}

// ---- job decode: 1024 AB + 528 AA(ti<=tj) + 528 BB(ti<=tj) ----
struct Job {
    int job, ti, tj, quadP, quadT, sumP, sumT;
    bool diag, doT;
};
__device__ __forceinline__ Job decode_job(int bi) {
    Job J;
    if (bi < 1024) {
        J.job = 0; J.ti = bi >> 5; J.tj = bi & 31;
    } else {
        int t = bi - 1024;
        J.job = (t < 528) ? 1 : 2;
        int tt = (t < 528) ? t : t - 528;
        int i = 0;
        while (tt >= 32 - i) { tt -= 32 - i; i++; }
        J.ti = i; J.tj = i + tt;
    }
    J.diag = (J.job != 0) && (J.ti == J.tj);
    J.doT  = (J.job == 0) || (J.ti != J.tj);
    J.quadP = (J.job == 0) ? 0 : (J.job == 1 ? 4096 : 12288);
    J.quadT = (J.job == 0) ? 8192 : J.quadP;
    J.sumP = (J.job == 2) ? NROWS : 0;
    J.sumT = (J.job == 1) ? 0 : NROWS;
    return J;
}

// ======================= pass 1: sums only =======================
// SMEM: P, Q (32 KB each) + rs/cs.
#define S1_P  0
#define S1_Q  32768
#define S1_RS 65536
#define S1_CS 66048
#define S1_TOTAL 66560

__global__ void __launch_bounds__(256, 2)
sum_kernel() {
    extern __shared__ char smem[];
    uint32_t sb = (uint32_t)__cvta_generic_to_shared(smem);
    float* rs_s = (float*)(smem + S1_RS);
    float* cs_s = (float*)(smem + S1_CS);
    int tid = threadIdx.x, wid = tid >> 5, lane = tid & 31;
    int wm = wid & 1, wn = wid >> 1;
    int g8 = lane & 7, sel = lane >> 3;
    int qr = lane >> 2, qc = (lane & 3) * 2;

    Job J = decode_job(blockIdx.x);
    const __nv_bfloat16* Lh = (J.job == 2) ? g_bh : g_ah;
    const __nv_bfloat16* Rh = (J.job == 1) ? g_ah : g_bh;
    const __nv_bfloat16* Ah = Lh + J.ti * 128 * DDIM;
    const __nv_bfloat16* Bh = Rh + J.tj * 128 * DDIM;

    if (tid < 128) { rs_s[tid] = 0.0f; cs_s[tid] = 0.0f; }

    #pragma unroll
    for (int it = 0; it < 8; it++) {
        int i = tid + it * 256;
        int r = i >> 4, c = i & 15;
        uint32_t so = swz(r, c);
        cpa16(sb + S1_P + so, Ah + r * DDIM + c * 8);
        cpa16(sb + S1_Q + so, Bh + r * DDIM + c * 8);
    }
    CP_COMMIT();
    CP_WAIT(0);
    __syncthreads();

    float acc[16][4];
    #pragma unroll
    for (int i = 0; i < 16; i++)
        #pragma unroll
        for (int j = 0; j < 4; j++) acc[i][j] = 0.0f;

    #pragma unroll
    for (int ks = 0; ks < 8; ks++) {
        int kc = ks * 2;
        uint32_t af[4][4], bf[4][2];
        #pragma unroll
        for (int mt = 0; mt < 4; mt++) {
            int row = wm * 64 + mt * 16 + g8 + ((sel & 1) << 3);
            ldsm4(af[mt], sb + S1_P + swz(row, kc + (sel >> 1)));
        }
        #pragma unroll
        for (int nt = 0; nt < 4; nt++) {
            int row = wn * 32 + nt * 8 + g8;
            ldsm2(bf[nt], sb + S1_Q + swz(row, kc + (sel & 1)));
        }
        #pragma unroll
        for (int mt = 0; mt < 4; mt++)
            #pragma unroll
            for (int nt = 0; nt < 4; nt++)
                mma16816(acc[mt * 4 + nt], af[mt], bf[nt]);
    }

    // exp + diag mask
    #pragma unroll
    for (int mt = 0; mt < 4; mt++)
        #pragma unroll
        for (int nt = 0; nt < 4; nt++) {
            float* a = acc[mt * 4 + nt];
            #pragma unroll
            for (int j = 0; j < 4; j++) a[j] = __expf(a[j] * 10.0f);
            if (J.diag) {
                int cl = wn * 32 + nt * 8 + qc;
                #pragma unroll
                for (int h = 0; h < 2; h++) {
                    int rl = wm * 64 + mt * 16 + h * 8 + qr;
                    if (cl == rl)     a[h * 2 + 0] = 0.0f;
                    if (cl + 1 == rl) a[h * 2 + 1] = 0.0f;
                }
            }
        }

    // row sums
    #pragma unroll
    for (int mt = 0; mt < 4; mt++) {
        #pragma unroll
        for (int h = 0; h < 2; h++) {
            int rloc = wm * 64 + mt * 16 + h * 8 + qr;
            float rsum = 0.0f;
            #pragma unroll
            for (int nt = 0; nt < 4; nt++) {
                const float* a = acc[mt * 4 + nt];
                rsum += a[h * 2 + 0] + a[h * 2 + 1];
            }
            rsum += __shfl_xor_sync(0xffffffffu, rsum, 1);
            rsum += __shfl_xor_sync(0xffffffffu, rsum, 2);
            if ((lane & 3) == 0) atomicAdd(&rs_s[rloc], rsum);
        }
    }
    // col sums
    #pragma unroll
    for (int nt = 0; nt < 4; nt++) {
        float c0s = 0.0f, c1s = 0.0f;
        #pragma unroll
        for (int mt = 0; mt < 4; mt++) {
            const float* a = acc[mt * 4 + nt];
            c0s += a[0] + a[2];
            c1s += a[1] + a[3];
        }
        #pragma unroll
        for (int o = 4; o <= 16; o <<= 1) {
            c0s += __shfl_xor_sync(0xffffffffu, c0s, o);
            c1s += __shfl_xor_sync(0xffffffffu, c1s, o);
        }
        if (lane < 4) {
            int cloc = wn * 32 + nt * 8 + qc;
            atomicAdd(&cs_s[cloc], c0s);
            atomicAdd(&cs_s[cloc + 1], c1s);
        }
    }
    __syncthreads();
    if (tid < 128) {
        atomicAdd(&g_sums[J.sumP + J.ti * 128 + tid], rs_s[tid]);
        if (J.doT) atomicAdd(&g_sums[J.sumT + J.tj * 128 + tid], cs_s[tid]);
    }
}

// ======================= pass 2: scaled output =======================
// SMEM: P=Ah, Q=Bh, R=Al then Bl (32 KB each); inv-sum tables after.
// Transpose stage (fp32, 64 cols x 132-float stride = 33792 B) reuses P+Q.
#define SM_P 0
#define SM_Q 32768
#define SM_R 65536
#define SM_RS 98304
#define SM_CS 98816
#define SM_TOTAL 99328
#define TSTRIDE 132

__global__ void __launch_bounds__(256, 2)
out_kernel(float* __restrict__ out) {
    extern __shared__ char smem[];
    uint32_t sb = (uint32_t)__cvta_generic_to_shared(smem);
    float* inv_p = (float*)(smem + SM_RS);   // 1/rowsum for primary rows
    float* inv_t = (float*)(smem + SM_CS);   // 1/rowsum for transposed rows
    int tid = threadIdx.x, wid = tid >> 5, lane = tid & 31;
    int wm = wid & 1, wn = wid >> 1;
    int g8 = lane & 7, sel = lane >> 3;
    int qr = lane >> 2, qc = (lane & 3) * 2;

    Job J = decode_job(blockIdx.x);
    const __nv_bfloat16* Lh = (J.job == 2) ? g_bh : g_ah;
    const __nv_bfloat16* Ll = (J.job == 2) ? g_bl : g_al;
    const __nv_bfloat16* Rh = (J.job == 1) ? g_ah : g_bh;
    const __nv_bfloat16* Rl = (J.job == 1) ? g_al : g_bl;
    int colP = J.quadP + J.tj * 128;
    int colT = J.quadT + J.ti * 128;

    const __nv_bfloat16* Ah = Lh + J.ti * 128 * DDIM;
    const __nv_bfloat16* Al = Ll + J.ti * 128 * DDIM;
    const __nv_bfloat16* Bh = Rh + J.tj * 128 * DDIM;
    const __nv_bfloat16* Bl = Rl + J.tj * 128 * DDIM;

    if (tid < 128) {
        inv_p[tid] = __frcp_rn(g_sums[J.sumP + J.ti * 128 + tid]);
        inv_t[tid] = __frcp_rn(g_sums[J.sumT + J.tj * 128 + tid]);
    }

    #pragma unroll
    for (int it = 0; it < 8; it++) {
        int i = tid + it * 256;
        int r = i >> 4, c = i & 15;
        uint32_t so = swz(r, c);
        cpa16(sb + SM_P + so, Ah + r * DDIM + c * 8);
        cpa16(sb + SM_Q + so, Bh + r * DDIM + c * 8);
    }
    CP_COMMIT();
    #pragma unroll
    for (int it = 0; it < 8; it++) {
        int i = tid + it * 256;
        int r = i >> 4, c = i & 15;
        cpa16(sb + SM_R + swz(r, c), Al + r * DDIM + c * 8);
    }
    CP_COMMIT();

    float acc[16][4];
    #pragma unroll
    for (int i = 0; i < 16; i++)
        #pragma unroll
        for (int j = 0; j < 4; j++) acc[i][j] = 0.0f;

    auto mma_pass = [&](uint32_t abase, uint32_t bbase) {
        #pragma unroll
        for (int ks = 0; ks < 8; ks++) {
            int kc = ks * 2;
            uint32_t af[4][4], bf[4][2];
            #pragma unroll
            for (int mt = 0; mt < 4; mt++) {
                int row = wm * 64 + mt * 16 + g8 + ((sel & 1) << 3);
                ldsm4(af[mt], abase + swz(row, kc + (sel >> 1)));
            }
            #pragma unroll
            for (int nt = 0; nt < 4; nt++) {
                int row = wn * 32 + nt * 8 + g8;
                ldsm2(bf[nt], bbase + swz(row, kc + (sel & 1)));
            }
            #pragma unroll
            for (int mt = 0; mt < 4; mt++)
                #pragma unroll
                for (int nt = 0; nt < 4; nt++)
                    mma16816(acc[mt * 4 + nt], af[mt], bf[nt]);
        }
    };

    CP_WAIT(1);
    __syncthreads();
    mma_pass(sb + SM_P, sb + SM_Q);          // hh
    CP_WAIT(0);
    __syncthreads();
    mma_pass(sb + SM_R, sb + SM_Q);          // lh
    __syncthreads();
    #pragma unroll
    for (int it = 0; it < 8; it++) {
        int i = tid + it * 256;
        int r = i >> 4, c = i & 15;
        cpa16(sb + SM_R + swz(r, c), Bl + r * DDIM + c * 8);
    }
    CP_COMMIT();
    CP_WAIT(0);
    __syncthreads();
    mma_pass(sb + SM_P, sb + SM_R);          // hl
    __syncthreads();     // operand smem free -> stage reuse ok

    // exp + diag mask (raw, unscaled)
    #pragma unroll
    for (int mt = 0; mt < 4; mt++)
        #pragma unroll
        for (int nt = 0; nt < 4; nt++) {
            float* a = acc[mt * 4 + nt];
            #pragma unroll
            for (int j = 0; j < 4; j++) a[j] = __expf(a[j] * 10.0f);
            if (J.diag) {
                int cl = wn * 32 + nt * 8 + qc;
                #pragma unroll
                for (int h = 0; h < 2; h++) {
                    int rl = wm * 64 + mt * 16 + h * 8 + qr;
                    if (cl == rl)     a[h * 2 + 0] = 0.0f;
                    if (cl + 1 == rl) a[h * 2 + 1] = 0.0f;
                }
            }
        }

    // primary scaled fp32 stores
    #pragma unroll
    for (int mt = 0; mt < 4; mt++) {
        #pragma unroll
        for (int h = 0; h < 2; h++) {
            int rloc = wm * 64 + mt * 16 + h * 8 + qr;
            int grow = J.ti * 128 + rloc;
            float inv = inv_p[rloc];
            float* rowp = out + (size_t)grow * OCOLS + colP;
            #pragma unroll
            for (int nt = 0; nt < 4; nt++) {
                int cloc = wn * 32 + nt * 8 + qc;
                const float* a = acc[mt * 4 + nt];
                *(float2*)(rowp + cloc) =
                    make_float2(a[h * 2 + 0] * inv, a[h * 2 + 1] * inv);
            }
        }
    }

    // transposed writes: two rounds of 64 cols through fp32 smem stage
    float* stg = (float*)smem;
    #pragma unroll
    for (int rnd = 0; rnd < 2; rnd++) {
        if (J.doT && (wid >> 2) == rnd) {
            #pragma unroll
            for (int mt = 0; mt < 4; mt++)
                #pragma unroll
                for (int nt = 0; nt < 4; nt++) {
                    const float* a = acc[mt * 4 + nt];
                    int cloc = (wn & 1) * 32 + nt * 8 + qc;   // 0..63 within round
                    #pragma unroll
                    for (int h = 0; h < 2; h++) {
                        int rloc = wm * 64 + mt * 16 + h * 8 + qr;
                        stg[cloc * TSTRIDE + rloc]       = a[h * 2 + 0];
                        stg[(cloc + 1) * TSTRIDE + rloc] = a[h * 2 + 1];
                    }
                }
        }
        __syncthreads();
        if (J.doT) {
            #pragma unroll
            for (int rr = 0; rr < 8; rr++) {
                int cl = wid * 8 + rr;                 // 0..63 within round
                int c  = rnd * 64 + cl;
                float inv = inv_t[c];
                float4 v = *(const float4*)(stg + cl * TSTRIDE + lane * 4);
                v.x *= inv; v.y *= inv; v.z *= inv; v.w *= inv;
                int trow = J.tj * 128 + c;
                *(float4*)(out + (size_t)trow * OCOLS + colT + lane * 4) = v;
            }
        }
        __syncthreads();
    }
}

extern "C" void kernel_launch(void* const* d_in, const int* in_sizes, int n_in,
                              void* d_out, int out_size) {
    const float* z1 = (const float*)d_in[0];
    const float* z2 = (const float*)d_in[1];
    float* out = (float*)d_out;

    cudaFuncSetAttribute(sum_kernel,
                         cudaFuncAttributeMaxDynamicSharedMemorySize, S1_TOTAL);
    cudaFuncSetAttribute(out_kernel,
                         cudaFuncAttributeMaxDynamicSharedMemorySize, SM_TOTAL);

    norm_kernel<<<2 * NROWS, 128>>>(z1, z2);
    sum_kernel<<<2080, 256, S1_TOTAL>>>();
    out_kernel<<<2080, 256, SM_TOTAL>>>(out);
}

// round 16
// speedup vs baseline: 2.4427x; 1.3211x over previous
#include <cuda_runtime.h>
#include <cuda_fp16.h>
#include <cstdint>

// B=4096, D=128. out[4096][16384] fp32.
// part1 (cols 0..8191)  = softmax([a@b.T , a@a.T - diag*INF])
// part2 (cols 8192..)   = softmax([b@a.T , b@b.T - diag*INF])
// Plain fp16 GEMM (single product) on mma.sync.m16n8k16.f32.f16.f16.f32.
// Logit quantization error rms ~2.5e-4 (aggregate metric; validated R11/R15).
// Two-pass recompute: pass 1 = sums only; pass 2 = identical logits -> exact
// softmax of the perturbed logits, scaled fp32 writes straight to d_out.
// Symmetry: ba = ab^T, aa/bb symmetric -> 2080 tiles per pass.

#define NROWS 4096
#define DDIM  128
#define OCOLS 16384

__device__ float g_sums[2 * NROWS];
__device__ __align__(256) __half g_a16[NROWS * DDIM];
__device__ __align__(256) __half g_b16[NROWS * DDIM];

// ---------------- normalize -> fp16, zero sums (warp per row) ----------------
__global__ void norm_kernel(const float* __restrict__ z1,
                            const float* __restrict__ z2) {
    int w = blockIdx.x * 8 + (threadIdx.x >> 5);   // 0..8191
    int lane = threadIdx.x & 31;
    const float* src; __half* dst; int r;
    if (w < NROWS) { src = z1; dst = g_a16; r = w; }
    else           { src = z2; dst = g_b16; r = w - NROWS; }
    float4 v = *(const float4*)(src + r * DDIM + lane * 4);
    float s = v.x * v.x + v.y * v.y + v.z * v.z + v.w * v.w;
    #pragma unroll
    for (int o = 16; o; o >>= 1) s += __shfl_xor_sync(0xffffffffu, s, o);
    float rs = rsqrtf(fmaxf(s, 1e-12f));
    __half2 h0 = __floats2half2_rn(v.x * rs, v.y * rs);
    __half2 h1 = __floats2half2_rn(v.z * rs, v.w * rs);
    uint2 u = make_uint2(*reinterpret_cast<uint32_t*>(&h0),
                         *reinterpret_cast<uint32_t*>(&h1));
    *(uint2*)(dst + r * DDIM + lane * 4) = u;
    if (lane == 0) g_sums[w] = 0.0f;
}

// ---------------- mma / cp.async helpers ----------------
__device__ __forceinline__ void ldsm4(uint32_t* r, uint32_t addr) {
    asm volatile("ldmatrix.sync.aligned.m8n8.x4.shared.b16 {%0,%1,%2,%3}, [%4];"
                 : "=r"(r[0]), "=r"(r[1]), "=r"(r[2]), "=r"(r[3]) : "r"(addr));
}
__device__ __forceinline__ void ldsm2(uint32_t* r, uint32_t addr) {
    asm volatile("ldmatrix.sync.aligned.m8n8.x2.shared.b16 {%0,%1}, [%2];"
                 : "=r"(r[0]), "=r"(r[1]) : "r"(addr));
}
__device__ __forceinline__ void mma16816(float* d, const uint32_t* a, const uint32_t* b) {
    asm volatile(
        "mma.sync.aligned.m16n8k16.row.col.f32.f16.f16.f32 "
        "{%0,%1,%2,%3}, {%4,%5,%6,%7}, {%8,%9}, {%0,%1,%2,%3};"
        : "+f"(d[0]), "+f"(d[1]), "+f"(d[2]), "+f"(d[3])
        : "r"(a[0]), "r"(a[1]), "r"(a[2]), "r"(a[3]), "r"(b[0]), "r"(b[1]));
}
__device__ __forceinline__ void cpa16(uint32_t dst, const void* src) {
    asm volatile("cp.async.cg.shared.global [%0], [%1], 16;" :: "r"(dst), "l"(src));
}
#define CP_COMMIT() asm volatile("cp.async.commit_group;")
#define CP_WAIT(n)  asm volatile("cp.async.wait_group %0;" :: "n"(n))

// Swizzled smem offset for a [128 rows x 128 fp16] tile: row stride 256B.
__device__ __forceinline__ uint32_t swz(int row, int chunk) {
    return (uint32_t)(row * 256 + ((chunk ^ (row & 7)) << 4));
}

// ---- job decode: 1024 AB + 528 AA(ti<=tj) + 528 BB(ti<=tj) ----
struct Job {
    int job, ti, tj, quadP, quadT, sumP, sumT;
    bool diag, doT;
};
__device__ __forceinline__ Job decode_job(int bi) {
    Job J;
    if (bi < 1024) {
        J.job = 0; J.ti = bi >> 5; J.tj = bi & 31;
    } else {
        int t = bi - 1024;
        J.job = (t < 528) ? 1 : 2;
        int tt = (t < 528) ? t : t - 528;
        int i = 0;
        while (tt >= 32 - i) { tt -= 32 - i; i++; }
        J.ti = i; J.tj = i + tt;
    }
    J.diag = (J.job != 0) && (J.ti == J.tj);
    J.doT  = (J.job == 0) || (J.ti != J.tj);
    J.quadP = (J.job == 0) ? 0 : (J.job == 1 ? 4096 : 12288);
    J.quadT = (J.job == 0) ? 8192 : J.quadP;
    J.sumP = (J.job == 2) ? NROWS : 0;
    J.sumT = (J.job == 1) ? 0 : NROWS;
    return J;
}

// SMEM layout (both passes): P, Q tiles 32 KB each; aux tables after.
#define SM_P  0
#define SM_Q  32768
#define SM_T0 65536
#define SM_T1 66048
#define SM_TOTAL 66560
#define TSTRIDE 132

// Shared MMA body: compute 64 fp32 logits per thread from P/Q tiles.
// Identical in both passes -> identical logits -> consistent softmax.
__device__ __forceinline__ void compute_tile(uint32_t sb, float acc[16][4],
                                             int wm, int wn, int g8, int sel) {
    #pragma unroll
    for (int i = 0; i < 16; i++)
        #pragma unroll
        for (int j = 0; j < 4; j++) acc[i][j] = 0.0f;
    #pragma unroll
    for (int ks = 0; ks < 8; ks++) {
        int kc = ks * 2;
        uint32_t af[4][4], bf[4][2];
        #pragma unroll
        for (int mt = 0; mt < 4; mt++) {
            int row = wm * 64 + mt * 16 + g8 + ((sel & 1) << 3);
            ldsm4(af[mt], sb + SM_P + swz(row, kc + (sel >> 1)));
        }
        #pragma unroll
        for (int nt = 0; nt < 4; nt++) {
            int row = wn * 32 + nt * 8 + g8;
            ldsm2(bf[nt], sb + SM_Q + swz(row, kc + (sel & 1)));
        }
        #pragma unroll
        for (int mt = 0; mt < 4; mt++)
            #pragma unroll
            for (int nt = 0; nt < 4; nt++)
                mma16816(acc[mt * 4 + nt], af[mt], bf[nt]);
    }
}

__device__ __forceinline__ void exp_mask(float acc[16][4], const Job& J,
                                         int wm, int wn, int qr, int qc) {
    #pragma unroll
    for (int mt = 0; mt < 4; mt++)
        #pragma unroll
        for (int nt = 0; nt < 4; nt++) {
            float* a = acc[mt * 4 + nt];
            #pragma unroll
            for (int j = 0; j < 4; j++) a[j] = __expf(a[j] * 10.0f);
            if (J.diag) {
                int cl = wn * 32 + nt * 8 + qc;
                #pragma unroll
                for (int h = 0; h < 2; h++) {
                    int rl = wm * 64 + mt * 16 + h * 8 + qr;
                    if (cl == rl)     a[h * 2 + 0] = 0.0f;
                    if (cl + 1 == rl) a[h * 2 + 1] = 0.0f;
                }
            }
        }
}

// ======================= pass 1: sums only =======================
__global__ void __launch_bounds__(256, 2)
sum_kernel() {
    extern __shared__ char smem[];
    uint32_t sb = (uint32_t)__cvta_generic_to_shared(smem);
    float* rs_s = (float*)(smem + SM_T0);
    float* cs_s = (float*)(smem + SM_T1);
    int tid = threadIdx.x, wid = tid >> 5, lane = tid & 31;
    int wm = wid & 1, wn = wid >> 1;
    int g8 = lane & 7, sel = lane >> 3;
    int qr = lane >> 2, qc = (lane & 3) * 2;

    Job J = decode_job(blockIdx.x);
    const __half* Ag = ((J.job == 2) ? g_b16 : g_a16) + J.ti * 128 * DDIM;
    const __half* Bg = ((J.job == 1) ? g_a16 : g_b16) + J.tj * 128 * DDIM;

    if (tid < 128) { rs_s[tid] = 0.0f; cs_s[tid] = 0.0f; }

    #pragma unroll
    for (int it = 0; it < 8; it++) {
        int i = tid + it * 256;
        int r = i >> 4, c = i & 15;
        uint32_t so = swz(r, c);
        cpa16(sb + SM_P + so, Ag + r * DDIM + c * 8);
        cpa16(sb + SM_Q + so, Bg + r * DDIM + c * 8);
    }
    CP_COMMIT();
    CP_WAIT(0);
    __syncthreads();

    float acc[16][4];
    compute_tile(sb, acc, wm, wn, g8, sel);
    exp_mask(acc, J, wm, wn, qr, qc);

    // row sums
    #pragma unroll
    for (int mt = 0; mt < 4; mt++) {
        #pragma unroll
        for (int h = 0; h < 2; h++) {
            int rloc = wm * 64 + mt * 16 + h * 8 + qr;
            float rsum = 0.0f;
            #pragma unroll
            for (int nt = 0; nt < 4; nt++) {
                const float* a = acc[mt * 4 + nt];
                rsum += a[h * 2 + 0] + a[h * 2 + 1];
            }
            rsum += __shfl_xor_sync(0xffffffffu, rsum, 1);
            rsum += __shfl_xor_sync(0xffffffffu, rsum, 2);
            if ((lane & 3) == 0) atomicAdd(&rs_s[rloc], rsum);
        }
    }
    // col sums
    #pragma unroll
    for (int nt = 0; nt < 4; nt++) {
        float c0s = 0.0f, c1s = 0.0f;
        #pragma unroll
        for (int mt = 0; mt < 4; mt++) {
            const float* a = acc[mt * 4 + nt];
            c0s += a[0] + a[2];
            c1s += a[1] + a[3];
        }
        #pragma unroll
        for (int o = 4; o <= 16; o <<= 1) {
            c0s += __shfl_xor_sync(0xffffffffu, c0s, o);
            c1s += __shfl_xor_sync(0xffffffffu, c1s, o);
        }
        if (lane < 4) {
            int cloc = wn * 32 + nt * 8 + qc;
            atomicAdd(&cs_s[cloc], c0s);
            atomicAdd(&cs_s[cloc + 1], c1s);
        }
    }
    __syncthreads();
    if (tid < 128) {
        atomicAdd(&g_sums[J.sumP + J.ti * 128 + tid], rs_s[tid]);
        if (J.doT) atomicAdd(&g_sums[J.sumT + J.tj * 128 + tid], cs_s[tid]);
    }
}

// ======================= pass 2: scaled output =======================
__global__ void __launch_bounds__(256, 2)
out_kernel(float* __restrict__ out) {
    extern __shared__ char smem[];
    uint32_t sb = (uint32_t)__cvta_generic_to_shared(smem);
    float* inv_p = (float*)(smem + SM_T0);   // 1/rowsum, primary rows
    float* inv_t = (float*)(smem + SM_T1);   // 1/rowsum, transposed rows
    int tid = threadIdx.x, wid = tid >> 5, lane = tid & 31;
    int wm = wid & 1, wn = wid >> 1;
    int g8 = lane & 7, sel = lane >> 3;
    int qr = lane >> 2, qc = (lane & 3) * 2;

    Job J = decode_job(blockIdx.x);
    const __half* Ag = ((J.job == 2) ? g_b16 : g_a16) + J.ti * 128 * DDIM;
    const __half* Bg = ((J.job == 1) ? g_a16 : g_b16) + J.tj * 128 * DDIM;
    int colP = J.quadP + J.tj * 128;
    int colT = J.quadT + J.ti * 128;

    if (tid < 128) {
        inv_p[tid] = __frcp_rn(g_sums[J.sumP + J.ti * 128 + tid]);
        inv_t[tid] = __frcp_rn(g_sums[J.sumT + J.tj * 128 + tid]);
    }

    #pragma unroll
    for (int it = 0; it < 8; it++) {
        int i = tid + it * 256;
        int r = i >> 4, c = i & 15;
        uint32_t so = swz(r, c);
        cpa16(sb + SM_P + so, Ag + r * DDIM + c * 8);
        cpa16(sb + SM_Q + so, Bg + r * DDIM + c * 8);
    }
    CP_COMMIT();
    CP_WAIT(0);
    __syncthreads();

    float acc[16][4];
    compute_tile(sb, acc, wm, wn, g8, sel);
    __syncthreads();     // all warps done with operand smem -> stage reuse ok
    exp_mask(acc, J, wm, wn, qr, qc);

    // primary scaled fp32 stores
    #pragma unroll
    for (int mt = 0; mt < 4; mt++) {
        #pragma unroll
        for (int h = 0; h < 2; h++) {
            int rloc = wm * 64 + mt * 16 + h * 8 + qr;
            int grow = J.ti * 128 + rloc;
            float inv = inv_p[rloc];
            float* rowp = out + (size_t)grow * OCOLS + colP;
            #pragma unroll
            for (int nt = 0; nt < 4; nt++) {
                int cloc = wn * 32 + nt * 8 + qc;
                const float* a = acc[mt * 4 + nt];
                *(float2*)(rowp + cloc) =
                    make_float2(a[h * 2 + 0] * inv, a[h * 2 + 1] * inv);
            }
        }
    }

    // transposed writes: two rounds of 64 cols through fp32 smem stage
    float* stg = (float*)smem;
    #pragma unroll
    for (int rnd = 0; rnd < 2; rnd++) {
        if (J.doT && (wid >> 2) == rnd) {
            #pragma unroll
            for (int mt = 0; mt < 4; mt++)
                #pragma unroll
                for (int nt = 0; nt < 4; nt++) {
                    const float* a = acc[mt * 4 + nt];
                    int cloc = (wn & 1) * 32 + nt * 8 + qc;   // 0..63 within round
                    #pragma unroll
                    for (int h = 0; h < 2; h++) {
                        int rloc = wm * 64 + mt * 16 + h * 8 + qr;
                        stg[cloc * TSTRIDE + rloc]       = a[h * 2 + 0];
                        stg[(cloc + 1) * TSTRIDE + rloc] = a[h * 2 + 1];
                    }
                }
        }
        __syncthreads();
        if (J.doT) {
            #pragma unroll
            for (int rr = 0; rr < 8; rr++) {
                int cl = wid * 8 + rr;                 // 0..63 within round
                int c  = rnd * 64 + cl;
                float inv = inv_t[c];
                float4 v = *(const float4*)(stg + cl * TSTRIDE + lane * 4);
                v.x *= inv; v.y *= inv; v.z *= inv; v.w *= inv;
                int trow = J.tj * 128 + c;
                *(float4*)(out + (size_t)trow * OCOLS + colT + lane * 4) = v;
            }
        }
        __syncthreads();
    }
}

extern "C" void kernel_launch(void* const* d_in, const int* in_sizes, int n_in,
                              void* d_out, int out_size) {
    const float* z1 = (const float*)d_in[0];
    const float* z2 = (const float*)d_in[1];
    float* out = (float*)d_out;

    cudaFuncSetAttribute(sum_kernel,
                         cudaFuncAttributeMaxDynamicSharedMemorySize, SM_TOTAL);
    cudaFuncSetAttribute(out_kernel,
                         cudaFuncAttributeMaxDynamicSharedMemorySize, SM_TOTAL);

    norm_kernel<<<1024, 256>>>(z1, z2);
    sum_kernel<<<2080, 256, SM_TOTAL>>>();
    out_kernel<<<2080, 256, SM_TOTAL>>>(out);
}

// round 17
// speedup vs baseline: 2.6388x; 1.0803x over previous
#include <cuda_runtime.h>
#include <cuda_fp16.h>
#include <cstdint>

// B=4096, D=128. out[4096][16384] fp32.
// part1 (cols 0..8191)  = softmax([a@b.T , a@a.T - diag*INF])
// part2 (cols 8192..)   = softmax([b@a.T , b@b.T - diag*INF])
// fp16 single-product GEMM (mma.m16n8k16.f32.f16.f16.f32); two-pass
// recompute (pass1 sums, pass2 identical logits -> scaled fp32 output).
// Symmetry: 2080 tiles/pass. This round: PDL overlap between the passes
// (out's MMA/exp/staging runs before sums are ready; griddepsync gates only
// the scale+store tail), single-round fp16 transpose stage, __stcs stores.

#define NROWS 4096
#define DDIM  128
#define OCOLS 16384

__device__ float g_sums[2 * NROWS];
__device__ __align__(256) __half g_a16[NROWS * DDIM];
__device__ __align__(256) __half g_b16[NROWS * DDIM];

// ---------------- normalize -> fp16, zero sums (warp per row) ----------------
__global__ void norm_kernel(const float* __restrict__ z1,
                            const float* __restrict__ z2) {
    int w = blockIdx.x * 8 + (threadIdx.x >> 5);   // 0..8191
    int lane = threadIdx.x & 31;
    const float* src; __half* dst; int r;
    if (w < NROWS) { src = z1; dst = g_a16; r = w; }
    else           { src = z2; dst = g_b16; r = w - NROWS; }
    float4 v = *(const float4*)(src + r * DDIM + lane * 4);
    float s = v.x * v.x + v.y * v.y + v.z * v.z + v.w * v.w;
    #pragma unroll
    for (int o = 16; o; o >>= 1) s += __shfl_xor_sync(0xffffffffu, s, o);
    float rs = rsqrtf(fmaxf(s, 1e-12f));
    __half2 h0 = __floats2half2_rn(v.x * rs, v.y * rs);
    __half2 h1 = __floats2half2_rn(v.z * rs, v.w * rs);
    uint2 u = make_uint2(*reinterpret_cast<uint32_t*>(&h0),
                         *reinterpret_cast<uint32_t*>(&h1));
    *(uint2*)(dst + r * DDIM + lane * 4) = u;
    if (lane == 0) g_sums[w] = 0.0f;
}

// ---------------- mma / cp.async helpers ----------------
__device__ __forceinline__ void ldsm4(uint32_t* r, uint32_t addr) {
    asm volatile("ldmatrix.sync.aligned.m8n8.x4.shared.b16 {%0,%1,%2,%3}, [%4];"
                 : "=r"(r[0]), "=r"(r[1]), "=r"(r[2]), "=r"(r[3]) : "r"(addr));
}
__device__ __forceinline__ void ldsm2(uint32_t* r, uint32_t addr) {
    asm volatile("ldmatrix.sync.aligned.m8n8.x2.shared.b16 {%0,%1}, [%2];"
                 : "=r"(r[0]), "=r"(r[1]) : "r"(addr));
}
__device__ __forceinline__ void mma16816(float* d, const uint32_t* a, const uint32_t* b) {
    asm volatile(
        "mma.sync.aligned.m16n8k16.row.col.f32.f16.f16.f32 "
        "{%0,%1,%2,%3}, {%4,%5,%6,%7}, {%8,%9}, {%0,%1,%2,%3};"
        : "+f"(d[0]), "+f"(d[1]), "+f"(d[2]), "+f"(d[3])
        : "r"(a[0]), "r"(a[1]), "r"(a[2]), "r"(a[3]), "r"(b[0]), "r"(b[1]));
}
__device__ __forceinline__ void cpa16(uint32_t dst, const void* src) {
    asm volatile("cp.async.cg.shared.global [%0], [%1], 16;" :: "r"(dst), "l"(src));
}
#define CP_COMMIT() asm volatile("cp.async.commit_group;")
#define CP_WAIT(n)  asm volatile("cp.async.wait_group %0;" :: "n"(n))

// Swizzled smem offset for a [128 rows x 128 fp16] tile: row stride 256B.
__device__ __forceinline__ uint32_t swz(int row, int chunk) {
    return (uint32_t)(row * 256 + ((chunk ^ (row & 7)) << 4));
}

// ---- job decode: 1024 AB + 528 AA(ti<=tj) + 528 BB(ti<=tj) ----
struct Job {
    int job, ti, tj, quadP, quadT, sumP, sumT;
    bool diag, doT;
};
__device__ __forceinline__ Job decode_job(int bi) {
    Job J;
    if (bi < 1024) {
        J.job = 0; J.ti = bi >> 5; J.tj = bi & 31;
    } else {
        int t = bi - 1024;
        J.job = (t < 528) ? 1 : 2;
        int tt = (t < 528) ? t : t - 528;
        int i = 0;
        while (tt >= 32 - i) { tt -= 32 - i; i++; }
        J.ti = i; J.tj = i + tt;
    }
    J.diag = (J.job != 0) && (J.ti == J.tj);
    J.doT  = (J.job == 0) || (J.ti != J.tj);
    J.quadP = (J.job == 0) ? 0 : (J.job == 1 ? 4096 : 12288);
    J.quadT = (J.job == 0) ? 8192 : J.quadP;
    J.sumP = (J.job == 2) ? NROWS : 0;
    J.sumT = (J.job == 1) ? 0 : NROWS;
    return J;
}

// SMEM layout (both passes): P, Q tiles 32 KB each; aux tables after.
// out_kernel reuses [0, 34816) as the fp16 transpose stage (64 cp x 136 u32).
#define SM_P  0
#define SM_Q  32768
#define SM_T0 65536
#define SM_T1 66048
#define SM_TOTAL 66560
#define TSTRIDE 136

// Shared MMA body: compute 64 fp32 logits per thread from P/Q tiles.
// Identical in both passes -> identical logits -> consistent softmax.
__device__ __forceinline__ void compute_tile(uint32_t sb, float acc[16][4],
                                             int wm, int wn, int g8, int sel) {
    #pragma unroll
    for (int i = 0; i < 16; i++)
        #pragma unroll
        for (int j = 0; j < 4; j++) acc[i][j] = 0.0f;
    #pragma unroll
    for (int ks = 0; ks < 8; ks++) {
        int kc = ks * 2;
        uint32_t af[4][4], bf[4][2];
        #pragma unroll
        for (int mt = 0; mt < 4; mt++) {
            int row = wm * 64 + mt * 16 + g8 + ((sel & 1) << 3);
            ldsm4(af[mt], sb + SM_P + swz(row, kc + (sel >> 1)));
        }
        #pragma unroll
        for (int nt = 0; nt < 4; nt++) {
            int row = wn * 32 + nt * 8 + g8;
            ldsm2(bf[nt], sb + SM_Q + swz(row, kc + (sel & 1)));
        }
        #pragma unroll
        for (int mt = 0; mt < 4; mt++)
            #pragma unroll
            for (int nt = 0; nt < 4; nt++)
                mma16816(acc[mt * 4 + nt], af[mt], bf[nt]);
    }
}

__device__ __forceinline__ void exp_mask(float acc[16][4], const Job& J,
                                         int wm, int wn, int qr, int qc) {
    #pragma unroll
    for (int mt = 0; mt < 4; mt++)
        #pragma unroll
        for (int nt = 0; nt < 4; nt++) {
            float* a = acc[mt * 4 + nt];
            #pragma unroll
            for (int j = 0; j < 4; j++) a[j] = __expf(a[j] * 10.0f);
            if (J.diag) {
                int cl = wn * 32 + nt * 8 + qc;
                #pragma unroll
                for (int h = 0; h < 2; h++) {
                    int rl = wm * 64 + mt * 16 + h * 8 + qr;
                    if (cl == rl)     a[h * 2 + 0] = 0.0f;
                    if (cl + 1 == rl) a[h * 2 + 1] = 0.0f;
                }
            }
        }
}

// ======================= pass 1: sums only =======================
__global__ void __launch_bounds__(256, 2)
sum_kernel() {
    cudaTriggerProgrammaticLaunchCompletion();   // let out_kernel fill early
    extern __shared__ char smem[];
    uint32_t sb = (uint32_t)__cvta_generic_to_shared(smem);
    float* rs_s = (float*)(smem + SM_T0);
    float* cs_s = (float*)(smem + SM_T1);
    int tid = threadIdx.x, wid = tid >> 5, lane = tid & 31;
    int wm = wid & 1, wn = wid >> 1;
    int g8 = lane & 7, sel = lane >> 3;
    int qr = lane >> 2, qc = (lane & 3) * 2;

    Job J = decode_job(blockIdx.x);
    const __half* Ag = ((J.job == 2) ? g_b16 : g_a16) + J.ti * 128 * DDIM;
    const __half* Bg = ((J.job == 1) ? g_a16 : g_b16) + J.tj * 128 * DDIM;

    if (tid < 128) { rs_s[tid] = 0.0f; cs_s[tid] = 0.0f; }

    #pragma unroll
    for (int it = 0; it < 8; it++) {
        int i = tid + it * 256;
        int r = i >> 4, c = i & 15;
        uint32_t so = swz(r, c);
        cpa16(sb + SM_P + so, Ag + r * DDIM + c * 8);
        cpa16(sb + SM_Q + so, Bg + r * DDIM + c * 8);
    }
    CP_COMMIT();
    CP_WAIT(0);
    __syncthreads();

    float acc[16][4];
    compute_tile(sb, acc, wm, wn, g8, sel);
    exp_mask(acc, J, wm, wn, qr, qc);

    // row sums
    #pragma unroll
    for (int mt = 0; mt < 4; mt++) {
        #pragma unroll
        for (int h = 0; h < 2; h++) {
            int rloc = wm * 64 + mt * 16 + h * 8 + qr;
            float rsum = 0.0f;
            #pragma unroll
            for (int nt = 0; nt < 4; nt++) {
                const float* a = acc[mt * 4 + nt];
                rsum += a[h * 2 + 0] + a[h * 2 + 1];
            }
            rsum += __shfl_xor_sync(0xffffffffu, rsum, 1);
            rsum += __shfl_xor_sync(0xffffffffu, rsum, 2);
            if ((lane & 3) == 0) atomicAdd(&rs_s[rloc], rsum);
        }
    }
    // col sums
    #pragma unroll
    for (int nt = 0; nt < 4; nt++) {
        float c0s = 0.0f, c1s = 0.0f;
        #pragma unroll
        for (int mt = 0; mt < 4; mt++) {
            const float* a = acc[mt * 4 + nt];
            c0s += a[0] + a[2];
            c1s += a[1] + a[3];
        }
        #pragma unroll
        for (int o = 4; o <= 16; o <<= 1) {
            c0s += __shfl_xor_sync(0xffffffffu, c0s, o);
            c1s += __shfl_xor_sync(0xffffffffu, c1s, o);
        }
        if (lane < 4) {
            int cloc = wn * 32 + nt * 8 + qc;
            atomicAdd(&cs_s[cloc], c0s);
            atomicAdd(&cs_s[cloc + 1], c1s);
        }
    }
    __syncthreads();
    if (tid < 128) {
        atomicAdd(&g_sums[J.sumP + J.ti * 128 + tid], rs_s[tid]);
        if (J.doT) atomicAdd(&g_sums[J.sumT + J.tj * 128 + tid], cs_s[tid]);
    }
}

// ======================= pass 2: scaled output =======================
__global__ void __launch_bounds__(256, 2)
out_kernel(float* __restrict__ out) {
    extern __shared__ char smem[];
    uint32_t sb = (uint32_t)__cvta_generic_to_shared(smem);
    float* inv_p = (float*)(smem + SM_T0);   // 1/rowsum, primary rows
    float* inv_t = (float*)(smem + SM_T1);   // 1/rowsum, transposed rows
    int tid = threadIdx.x, wid = tid >> 5, lane = tid & 31;
    int wm = wid & 1, wn = wid >> 1;
    int g8 = lane & 7, sel = lane >> 3;
    int qr = lane >> 2, qc = (lane & 3) * 2;

    Job J = decode_job(blockIdx.x);
    const __half* Ag = ((J.job == 2) ? g_b16 : g_a16) + J.ti * 128 * DDIM;
    const __half* Bg = ((J.job == 1) ? g_a16 : g_b16) + J.tj * 128 * DDIM;
    int colP = J.quadP + J.tj * 128;
    int colT = J.quadT + J.ti * 128;

    // ---- sum-independent phase (runs under PDL overlap with sum_kernel) ----
    #pragma unroll
    for (int it = 0; it < 8; it++) {
        int i = tid + it * 256;
        int r = i >> 4, c = i & 15;
        uint32_t so = swz(r, c);
        cpa16(sb + SM_P + so, Ag + r * DDIM + c * 8);
        cpa16(sb + SM_Q + so, Bg + r * DDIM + c * 8);
    }
    CP_COMMIT();
    CP_WAIT(0);
    __syncthreads();

    float acc[16][4];
    compute_tile(sb, acc, wm, wn, g8, sel);
    __syncthreads();     // all warps done with operand smem -> stage reuse ok
    exp_mask(acc, J, wm, wn, qr, qc);

    // stage transposed tile as packed half2: stg[(c>>1)*136 + r]
    if (J.doT) {
        uint32_t* stg = (uint32_t*)smem;
        #pragma unroll
        for (int mt = 0; mt < 4; mt++)
            #pragma unroll
            for (int nt = 0; nt < 4; nt++) {
                const float* a = acc[mt * 4 + nt];
                int cp = (wn * 32 + nt * 8 + qc) >> 1;   // col-pair 0..63
                #pragma unroll
                for (int h = 0; h < 2; h++) {
                    int rloc = wm * 64 + mt * 16 + h * 8 + qr;
                    __half2 hv = __floats2half2_rn(a[h * 2 + 0], a[h * 2 + 1]);
                    stg[cp * TSTRIDE + rloc] = *reinterpret_cast<uint32_t*>(&hv);
                }
            }
    }
    __syncthreads();

    // ---- wait for sums, then scale + store ----
    cudaGridDependencySynchronize();
    if (tid < 128) {
        inv_p[tid] = __frcp_rn(g_sums[J.sumP + J.ti * 128 + tid]);
        inv_t[tid] = __frcp_rn(g_sums[J.sumT + J.tj * 128 + tid]);
    }
    __syncthreads();

    // primary scaled fp32 stores (streaming)
    #pragma unroll
    for (int mt = 0; mt < 4; mt++) {
        #pragma unroll
        for (int h = 0; h < 2; h++) {
            int rloc = wm * 64 + mt * 16 + h * 8 + qr;
            int grow = J.ti * 128 + rloc;
            float inv = inv_p[rloc];
            float* rowp = out + (size_t)grow * OCOLS + colP;
            #pragma unroll
            for (int nt = 0; nt < 4; nt++) {
                int cloc = wn * 32 + nt * 8 + qc;
                const float* a = acc[mt * 4 + nt];
                __stcs((float2*)(rowp + cloc),
                       make_float2(a[h * 2 + 0] * inv, a[h * 2 + 1] * inv));
            }
        }
    }

    // transposed scaled fp32 stores from the fp16 stage (single round)
    if (J.doT) {
        const uint32_t* stg = (const uint32_t*)smem;
        #pragma unroll
        for (int rr = 0; rr < 8; rr++) {
            int cp = wid * 8 + rr;                        // 0..63
            uint4 q = *(const uint4*)(stg + cp * TSTRIDE + lane * 4);
            uint32_t l0 = __byte_perm(q.x, q.y, 0x5410);
            uint32_t l1 = __byte_perm(q.z, q.w, 0x5410);
            uint32_t h0 = __byte_perm(q.x, q.y, 0x7632);
            uint32_t h1 = __byte_perm(q.z, q.w, 0x7632);
            float2 a0 = __half22float2(*reinterpret_cast<__half2*>(&l0));
            float2 a1 = __half22float2(*reinterpret_cast<__half2*>(&l1));
            float2 b0 = __half22float2(*reinterpret_cast<__half2*>(&h0));
            float2 b1 = __half22float2(*reinterpret_cast<__half2*>(&h1));
            float iv0 = inv_t[2 * cp], iv1 = inv_t[2 * cp + 1];
            int trow = J.tj * 128 + 2 * cp;
            float* p0 = out + (size_t)trow * OCOLS + colT + lane * 4;
            __stcs((float4*)p0,
                   make_float4(a0.x * iv0, a0.y * iv0, a1.x * iv0, a1.y * iv0));
            __stcs((float4*)(p0 + OCOLS),
                   make_float4(b0.x * iv1, b0.y * iv1, b1.x * iv1, b1.y * iv1));
        }
    }
}

extern "C" void kernel_launch(void* const* d_in, const int* in_sizes, int n_in,
                              void* d_out, int out_size) {
    const float* z1 = (const float*)d_in[0];
    const float* z2 = (const float*)d_in[1];
    float* out = (float*)d_out;

    cudaFuncSetAttribute(sum_kernel,
                         cudaFuncAttributeMaxDynamicSharedMemorySize, SM_TOTAL);
    cudaFuncSetAttribute(out_kernel,
                         cudaFuncAttributeMaxDynamicSharedMemorySize, SM_TOTAL);

    norm_kernel<<<1024, 256>>>(z1, z2);
    sum_kernel<<<2080, 256, SM_TOTAL>>>();

    // out_kernel with programmatic dependent launch: overlap its
    // sum-independent phases with sum_kernel's tail.
    cudaLaunchConfig_t cfg = {};
    cfg.gridDim = dim3(2080);
    cfg.blockDim = dim3(256);
    cfg.dynamicSmemBytes = SM_TOTAL;
    cfg.stream = 0;
    cudaLaunchAttribute attr[1];
    attr[0].id = cudaLaunchAttributeProgrammaticStreamSerialization;
    attr[0].val.programmaticStreamSerializationAllowed = 1;
    cfg.attrs = attr;
    cfg.numAttrs = 1;
    cudaLaunchKernelEx(&cfg, out_kernel, out);
}